// round 3
// baseline (speedup 1.0000x reference)
#include <cuda_runtime.h>
#include <cuda_bf16.h>
#include <math.h>

#define NTOK  3072
#define UNITS 1024
#define NHEAD 16
#define HDIM  64
#define NBLK  64
#define CHK   32

__device__ float g_Q[NTOK * UNITS];
__device__ float g_K[NTOK * UNITS];
__device__ float g_V[NTOK * UNITS];
__device__ float g_O[NTOK * UNITS];
__device__ int   g_cnt[NBLK];
__device__ int   g_off[NBLK];
__device__ int   g_mem[NTOK];

// ---------------------------------------------------------------------------
__global__ void build_index_kernel(const int* __restrict__ ids) {
    __shared__ int s_cnt[NBLK];
    int b = threadIdx.x;
    int c = 0;
    for (int i = 0; i < NTOK; i++) c += (ids[i] == b) ? 1 : 0;
    s_cnt[b] = c;
    g_cnt[b] = c;
    __syncthreads();
    if (b == 0) {
        int acc = 0;
        for (int j = 0; j < NBLK; j++) { g_off[j] = acc; acc += s_cnt[j]; }
    }
    __syncthreads();
    int p = g_off[b];
    for (int i = 0; i < NTOK; i++)
        if (ids[i] == b) g_mem[p++] = i;
}

// ---------------------------------------------------------------------------
// TF32 tensor-core GEMM, double-buffered. C[M,N] = A[M,K] @ B[K,N].
// BM=128, BN=128, BK=16, 2 smem stages, ONE __syncthreads per K-tile.
// 256 threads = 8 warps (2x4), warp tile 64x32.
// K-within-8 permuted storage (pos = 2*(k%4) + k/4); XOR swizzles keep all
// fragment LDS.64 bank-conflict-free within half-warp phases.
// ---------------------------------------------------------------------------
__device__ __forceinline__ unsigned f2tf32(float f) {
    unsigned u;
    asm("cvt.rna.tf32.f32 %0, %1;" : "=r"(u) : "f"(f));
    return u;
}

struct GemmSmem {
    float As[2][128 * 24];      // [stage][m*24 + col]
    float Bs[2][2 * 128 * 8];   // [stage][ks*1024 + n*8 + pos]
};

__device__ __forceinline__ void gemm_body(
    const float* __restrict__ A, const float* __restrict__ B,
    float* __restrict__ C, int M, int NN, int K,
    GemmSmem* sm, int rowBase, int colBase)
{
    const int t    = threadIdx.x;
    const int lane = t & 31;
    const int warp = t >> 5;
    const int wr   = warp >> 2;
    const int wc   = warp & 3;
    const int r    = lane >> 2;
    const int cq   = lane & 3;

    // ---- A loader: thread covers (m = t>>1, k = (t&1)*8 .. +7) ----
    const int am  = t >> 1;            // 0..127
    const int ak8 = (t & 1) * 8;
    const float* Ag = A + (size_t)(rowBase + am) * K + ak8;
    int acol[8];
    {
        const int axm = 2 * (am & 3);
#pragma unroll
        for (int j = 0; j < 8; j++) {
            int p = 2 * (j & 3) + (j >> 2);
            acol[j] = ((ak8 + p)) ^ axm;    // ak8 contributes the ks bit (8)
        }
    }

    // ---- B loader: thread covers (k = t>>4, n = (t&15)*8 .. +7) ----
    const int bk  = t >> 4;            // 0..15
    const int bn0 = (t & 15) * 8;
    const float* Bg = B + (size_t)bk * NN + colBase + bn0;
    const int bks  = bk >> 3;          // 0..1
    const int pb   = 2 * (bk & 3) + ((bk & 7) >> 2);
    int bcol[8];
#pragma unroll
    for (int j = 0; j < 8; j++) {
        int n = bn0 + j;
        bcol[j] = bks * 1024 + n * 8 + (pb ^ ((n & 31) >> 2));
    }

    // ---- fragment smem offsets ----
    const int axr = (2 * cq) ^ (2 * (r & 3));
    int aoff[4][2];
#pragma unroll
    for (int i = 0; i < 4; i++) {
        int m0 = wr * 64 + i * 16 + r;
        aoff[i][0] = m0 * 24 + axr;
        aoff[i][1] = (m0 + 8) * 24 + axr;
    }
    int boff[4];
#pragma unroll
    for (int j = 0; j < 4; j++)
        boff[j] = (wc * 32 + j * 8 + r) * 8 + ((2 * cq) ^ (2 * j));
    const bool bswap = ((r >> 2) & 1) != 0;

    float acc[4][4][4];
#pragma unroll
    for (int i = 0; i < 4; i++)
#pragma unroll
        for (int j = 0; j < 4; j++)
#pragma unroll
            for (int e = 0; e < 4; e++) acc[i][j][e] = 0.f;

    // ---- load + store tile 0 ----
    {
        float4 a0 = *(const float4*)(Ag);
        float4 a1 = *(const float4*)(Ag + 4);
        float4 b0 = *(const float4*)(Bg);
        float4 b1 = *(const float4*)(Bg + 4);
        float va[8] = {a0.x, a0.y, a0.z, a0.w, a1.x, a1.y, a1.z, a1.w};
        float vb[8] = {b0.x, b0.y, b0.z, b0.w, b1.x, b1.y, b1.z, b1.w};
#pragma unroll
        for (int j = 0; j < 8; j++)
            sm->As[0][am * 24 + acol[j]] = __uint_as_float(f2tf32(va[j]));
#pragma unroll
        for (int j = 0; j < 8; j++)
            sm->Bs[0][bcol[j]] = __uint_as_float(f2tf32(vb[j]));
    }
    __syncthreads();

    const int nT = K / 16;
    for (int tt = 0; tt < nT; tt++) {
        const int cur = tt & 1;
        float4 na0, na1, nb0, nb1;
        const bool more = (tt + 1 < nT);
        if (more) {
            const int kn = (tt + 1) * 16;
            na0 = *(const float4*)(Ag + kn);
            na1 = *(const float4*)(Ag + kn + 4);
            nb0 = *(const float4*)(Bg + (size_t)kn * NN);
            nb1 = *(const float4*)(Bg + (size_t)kn * NN + 4);
        }

        // ---- compute on stage cur ----
        const float* Asc = sm->As[cur];
        const float* Bsc = sm->Bs[cur];
#pragma unroll
        for (int ks = 0; ks < 2; ks++) {
            unsigned af[4][4];
#pragma unroll
            for (int i = 0; i < 4; i++) {
                float2 a0 = *(const float2*)&Asc[aoff[i][0] + ks * 8];
                float2 a1 = *(const float2*)&Asc[aoff[i][1] + ks * 8];
                af[i][0] = __float_as_uint(a0.x);
                af[i][1] = __float_as_uint(a1.x);
                af[i][2] = __float_as_uint(a0.y);
                af[i][3] = __float_as_uint(a1.y);
            }
            unsigned bf[4][2];
#pragma unroll
            for (int j = 0; j < 4; j++) {
                float2 bv = *(const float2*)&Bsc[ks * 1024 + boff[j]];
                float b0 = bswap ? bv.y : bv.x;
                float b1 = bswap ? bv.x : bv.y;
                bf[j][0] = __float_as_uint(b0);
                bf[j][1] = __float_as_uint(b1);
            }
#pragma unroll
            for (int i = 0; i < 4; i++)
#pragma unroll
                for (int j = 0; j < 4; j++) {
                    asm volatile(
                        "mma.sync.aligned.m16n8k8.row.col.f32.tf32.tf32.f32 "
                        "{%0,%1,%2,%3}, {%4,%5,%6,%7}, {%8,%9}, {%0,%1,%2,%3};"
                        : "+f"(acc[i][j][0]), "+f"(acc[i][j][1]),
                          "+f"(acc[i][j][2]), "+f"(acc[i][j][3])
                        : "r"(af[i][0]), "r"(af[i][1]), "r"(af[i][2]), "r"(af[i][3]),
                          "r"(bf[j][0]), "r"(bf[j][1]));
                }
        }

        // ---- store next tile into other stage ----
        if (more) {
            float* Asn = sm->As[1 - cur];
            float* Bsn = sm->Bs[1 - cur];
            float va[8] = {na0.x, na0.y, na0.z, na0.w, na1.x, na1.y, na1.z, na1.w};
            float vb[8] = {nb0.x, nb0.y, nb0.z, nb0.w, nb1.x, nb1.y, nb1.z, nb1.w};
#pragma unroll
            for (int j = 0; j < 8; j++)
                Asn[am * 24 + acol[j]] = __uint_as_float(f2tf32(va[j]));
#pragma unroll
            for (int j = 0; j < 8; j++)
                Bsn[bcol[j]] = __uint_as_float(f2tf32(vb[j]));
        }
        __syncthreads();
    }

    // ---- epilogue ----
#pragma unroll
    for (int i = 0; i < 4; i++) {
        int row0 = rowBase + wr * 64 + i * 16 + r;
#pragma unroll
        for (int j = 0; j < 4; j++) {
            int col = colBase + wc * 32 + j * 8 + 2 * cq;
            *(float2*)&C[(size_t)row0 * NN + col] =
                make_float2(acc[i][j][0], acc[i][j][1]);
            *(float2*)&C[(size_t)(row0 + 8) * NN + col] =
                make_float2(acc[i][j][2], acc[i][j][3]);
        }
    }
}

__global__ __launch_bounds__(256, 2) void qkv_gemm(
    const float* __restrict__ x,
    const float* __restrict__ Wq, const float* __restrict__ Wk,
    const float* __restrict__ Wv)
{
    __shared__ GemmSmem sm;
    const int z = blockIdx.z;
    const float* B = (z == 0) ? Wq : (z == 1) ? Wk : Wv;
    float* C = (z == 0) ? g_Q : (z == 1) ? g_K : g_V;
    gemm_body(x, B, C, NTOK, UNITS, UNITS, &sm,
              blockIdx.y * 128, blockIdx.x * 128);
}

__global__ __launch_bounds__(256, 2) void out_gemm(
    const float* __restrict__ Wo, float* __restrict__ out)
{
    __shared__ GemmSmem sm;
    gemm_body(g_O, Wo, out, NTOK, UNITS, UNITS, &sm,
              blockIdx.y * 128, blockIdx.x * 128);
}

// ---------------------------------------------------------------------------
// Block-sparse attention: one CTA per (block, head), 64 threads (m avg ~48).
// ---------------------------------------------------------------------------
__global__ __launch_bounds__(64) void attn_kernel(const float* __restrict__ mask) {
    int b = blockIdx.x;
    int h = blockIdx.y;
    int m = g_cnt[b];
    if (m == 0) return;
    int off = g_off[b];

    __shared__ float Ks[CHK][HDIM];
    __shared__ float Vs[CHK][HDIM];
    __shared__ float Ss[64][CHK + 1];
    __shared__ float bs[CHK];

    int tid = threadIdx.x;

    for (int q0 = 0; q0 < m; q0 += 64) {
        int qi = q0 + tid;
        bool act = qi < m;
        int qt = act ? g_mem[off + qi] : g_mem[off];

        float qreg[HDIM];
        {
            const float4* qp = (const float4*)(g_Q + (size_t)qt * UNITS + h * HDIM);
#pragma unroll
            for (int i = 0; i < 16; i++) {
                float4 v = qp[i];
                qreg[4 * i + 0] = v.x; qreg[4 * i + 1] = v.y;
                qreg[4 * i + 2] = v.z; qreg[4 * i + 3] = v.w;
            }
        }

        float mx = -3e38f, sm = 0.f;
        float oacc[HDIM];
#pragma unroll
        for (int d = 0; d < HDIM; d++) oacc[d] = 0.f;

        for (int k0 = 0; k0 < m; k0 += CHK) {
            int cn = min(CHK, m - k0);
            __syncthreads();
            {
                int row = tid >> 1;          // 0..31
                int seg = (tid & 1) * 32;    // 0 or 32
                if (row < cn) {
                    int tk = g_mem[off + k0 + row];
                    const float4* kp = (const float4*)(g_K + (size_t)tk * UNITS + h * HDIM + seg);
                    const float4* vp = (const float4*)(g_V + (size_t)tk * UNITS + h * HDIM + seg);
#pragma unroll
                    for (int i = 0; i < 8; i++) {
                        ((float4*)&Ks[row][seg])[i] = kp[i];
                        ((float4*)&Vs[row][seg])[i] = vp[i];
                    }
                    if ((tid & 1) == 0)
                        bs[row] = (1.0f - mask[tk]) * (-1e9f);
                }
            }
            __syncthreads();

            float cm = -3e38f;
            for (int j = 0; j < cn; j++) {
                float s = 0.f;
#pragma unroll
                for (int d = 0; d < HDIM; d++) s += qreg[d] * Ks[j][d];
                s = s * 0.125f + bs[j];
                Ss[tid][j] = s;
                cm = fmaxf(cm, s);
            }
            float nm = fmaxf(mx, cm);
            float corr = __expf(mx - nm);
            sm *= corr;
#pragma unroll
            for (int d = 0; d < HDIM; d++) oacc[d] *= corr;
            for (int j = 0; j < cn; j++) {
                float p = __expf(Ss[tid][j] - nm);
                sm += p;
#pragma unroll
                for (int d = 0; d < HDIM; d++) oacc[d] += p * Vs[j][d];
            }
            mx = nm;
        }

        if (act) {
            float inv = 1.0f / sm;
            float* op = g_O + (size_t)qt * UNITS + h * HDIM;
#pragma unroll
            for (int i = 0; i < 16; i++) {
                float4 v = make_float4(oacc[4 * i + 0] * inv, oacc[4 * i + 1] * inv,
                                       oacc[4 * i + 2] * inv, oacc[4 * i + 3] * inv);
                *(float4*)(op + 4 * i) = v;
            }
        }
    }
}

// ---------------------------------------------------------------------------
extern "C" void kernel_launch(void* const* d_in, const int* in_sizes, int n_in,
                              void* d_out, int out_size)
{
    const float* x    = (const float*)d_in[0];
    const float* Wq   = (const float*)d_in[1];
    const float* Wk   = (const float*)d_in[2];
    const float* Wv   = (const float*)d_in[3];
    const float* Wo   = (const float*)d_in[4];
    const float* mask = (const float*)d_in[5];
    const int*   ids  = (const int*)d_in[6];
    float* out = (float*)d_out;

    build_index_kernel<<<1, NBLK>>>(ids);

    dim3 gq(UNITS / 128, NTOK / 128, 3);
    qkv_gemm<<<gq, 256>>>(x, Wq, Wk, Wv);

    attn_kernel<<<dim3(NBLK, NHEAD), 64>>>(mask);

    dim3 go(UNITS / 128, NTOK / 128);
    out_gemm<<<go, 256>>>(Wo, out);
}

// round 5
// speedup vs baseline: 1.2598x; 1.2598x over previous
#include <cuda_runtime.h>
#include <math.h>

#define NTOK  3072
#define UNITS 1024
#define NHEAD 16
#define HDIM  64
#define NBLK  64
#define CHK   32

// tf32-rounded operand pool: [x | Wq | Wk | Wv | Wo]
#define OFF_X  0
#define OFF_WQ (NTOK * UNITS)
#define OFF_WK (OFF_WQ + UNITS * UNITS)
#define OFF_WV (OFF_WK + UNITS * UNITS)
#define OFF_WO (OFF_WV + UNITS * UNITS)
#define TF_TOT (OFF_WO + UNITS * UNITS)

__device__ float g_tf[TF_TOT];
__device__ float g_QKV[3 * NTOK * UNITS];
__device__ float g_O[NTOK * UNITS];
__device__ int   g_cnt[NBLK];
__device__ int   g_off[NBLK];
__device__ int   g_mem[NTOK];

__device__ __forceinline__ unsigned f2tf32(float f) {
    unsigned u;
    asm("cvt.rna.tf32.f32 %0, %1;" : "=r"(u) : "f"(f));
    return u;
}

// ---------------------------------------------------------------------------
// Prep: round x + weights to tf32 once. 1835008 float4s = 7168 blocks x 256.
// ---------------------------------------------------------------------------
__global__ __launch_bounds__(256) void prep_kernel(
    const float* __restrict__ x,  const float* __restrict__ Wq,
    const float* __restrict__ Wk, const float* __restrict__ Wv,
    const float* __restrict__ Wo)
{
    int i = blockIdx.x * 256 + threadIdx.x;   // float4 index
    const float* src; int base;
    if      (i <  786432) { src = x;  base = 0;       }
    else if (i < 1048576) { src = Wq; base = 786432;  }
    else if (i < 1310720) { src = Wk; base = 1048576; }
    else if (i < 1572864) { src = Wv; base = 1310720; }
    else                  { src = Wo; base = 1572864; }
    float4 v = ((const float4*)src)[i - base];
    v.x = __uint_as_float(f2tf32(v.x));
    v.y = __uint_as_float(f2tf32(v.y));
    v.z = __uint_as_float(f2tf32(v.z));
    v.w = __uint_as_float(f2tf32(v.w));
    ((float4*)g_tf)[i] = v;
}

// ---------------------------------------------------------------------------
__global__ void build_index_kernel(const int* __restrict__ ids) {
    __shared__ int s_cnt[NBLK];
    int b = threadIdx.x;
    int c = 0;
    for (int i = 0; i < NTOK; i++) c += (ids[i] == b) ? 1 : 0;
    s_cnt[b] = c;
    g_cnt[b] = c;
    __syncthreads();
    if (b == 0) {
        int acc = 0;
        for (int j = 0; j < NBLK; j++) { g_off[j] = acc; acc += s_cnt[j]; }
    }
    __syncthreads();
    int p = g_off[b];
    for (int i = 0; i < NTOK; i++)
        if (ids[i] == b) g_mem[p++] = i;
}

// ---------------------------------------------------------------------------
// TF32 GEMM, cp.async 3-stage pipeline. C[M,N]=A[M,K]@B[K,N], inputs already
// tf32-rounded. BM=BN=128, BK=32, 256 threads = 8 warps (2x4), warp 64x32.
// Stage = A[128][32] (quad-swizzled: quad ^= m&7) + B[32][128] (n ^= 8*(k&3)).
// All fragment LDS.32 verified bank-conflict-free.
// ---------------------------------------------------------------------------
#define STAGE_F 8192   // floats per stage (A 4096 + B 4096)

__device__ __forceinline__ void cp16(float* dst, const float* src) {
    unsigned d = (unsigned)__cvta_generic_to_shared(dst);
    asm volatile("cp.async.cg.shared.global [%0], [%1], 16;" :: "r"(d), "l"(src));
}

__device__ __forceinline__ void gemm_body(
    const float* __restrict__ A, const float* __restrict__ B,
    float* __restrict__ C, int NN, int K,
    float* smem, int rowBase, int colBase)
{
    const int t    = threadIdx.x;
    const int lane = t & 31;
    const int warp = t >> 5;
    const int wr   = warp >> 2;
    const int wc   = warp & 3;
    const int r    = lane >> 2;
    const int cq   = lane & 3;

    // cp.async A: thread t copies row am = t>>1, 4 chunks from k = (t&1)*16
    const int am  = t >> 1;
    const int ak0 = (t & 1) * 16;
    const float* Ag = A + (size_t)(rowBase + am) * K + ak0;
    int adst[4];
#pragma unroll
    for (int j = 0; j < 4; j++) {
        int kc = (t & 1) * 4 + j;                 // chunk index 0..7
        adst[j] = am * 32 + ((kc ^ (am & 7)) * 4);
    }
    // cp.async B: thread t copies k-row bkr = t>>3, 4 chunks from n4 = (t&7)*4
    const int bkr  = t >> 3;
    const int bn40 = (t & 7) * 4;
    const float* Bg = B + (size_t)bkr * NN + colBase + bn40 * 4;
    int bdst[4];
#pragma unroll
    for (int j = 0; j < 4; j++) {
        int n4 = bn40 + j;
        bdst[j] = bkr * 128 + ((n4 ^ (2 * (bkr & 3))) * 4);
    }

    // fragment bases
    int a_b0[4], a_b8[4];
#pragma unroll
    for (int i = 0; i < 4; i++) {
        int m0 = wr * 64 + i * 16 + r;
        a_b0[i] = m0 * 32 + cq;
        a_b8[i] = (m0 + 8) * 32 + cq;
    }
    int b_n[4];
#pragma unroll
    for (int j = 0; j < 4; j++)
        b_n[j] = wc * 32 + ((j * 8 + r) ^ (8 * cq));

    float acc[4][4][4];
#pragma unroll
    for (int i = 0; i < 4; i++)
#pragma unroll
        for (int j = 0; j < 4; j++)
#pragma unroll
            for (int e = 0; e < 4; e++) acc[i][j][e] = 0.f;

    const int nT = K / 32;

    // prologue: tiles 0,1
#pragma unroll
    for (int pt = 0; pt < 2; pt++) {
        float* As = smem + pt * STAGE_F;
        float* Bs = As + 4096;
        const int ko = pt * 32;
#pragma unroll
        for (int j = 0; j < 4; j++) cp16(As + adst[j], Ag + ko + j * 4);
#pragma unroll
        for (int j = 0; j < 4; j++) cp16(Bs + bdst[j], Bg + (size_t)ko * NN + j * 4);
        asm volatile("cp.async.commit_group;" ::: "memory");
    }

    for (int tt = 0; tt < nT; tt++) {
        asm volatile("cp.async.wait_group 1;" ::: "memory");
        __syncthreads();

        if (tt + 2 < nT) {
            int st = (tt + 2) % 3;
            float* As = smem + st * STAGE_F;
            float* Bs = As + 4096;
            const int ko = (tt + 2) * 32;
#pragma unroll
            for (int j = 0; j < 4; j++) cp16(As + adst[j], Ag + ko + j * 4);
#pragma unroll
            for (int j = 0; j < 4; j++) cp16(Bs + bdst[j], Bg + (size_t)ko * NN + j * 4);
        }
        asm volatile("cp.async.commit_group;" ::: "memory");

        const float* As = smem + (tt % 3) * STAGE_F;
        const float* Bs = As + 4096;
#pragma unroll
        for (int ks = 0; ks < 4; ks++) {
            const int q0 = ((2 * ks) ^ r) * 4;
            const int q1 = ((2 * ks + 1) ^ r) * 4;
            unsigned af[4][4];
#pragma unroll
            for (int i = 0; i < 4; i++) {
                af[i][0] = __float_as_uint(As[a_b0[i] + q0]);
                af[i][1] = __float_as_uint(As[a_b8[i] + q0]);
                af[i][2] = __float_as_uint(As[a_b0[i] + q1]);
                af[i][3] = __float_as_uint(As[a_b8[i] + q1]);
            }
            const int kr0 = (ks * 8 + cq) * 128;
            const int kr1 = kr0 + 4 * 128;
            unsigned bf[4][2];
#pragma unroll
            for (int j = 0; j < 4; j++) {
                bf[j][0] = __float_as_uint(Bs[kr0 + b_n[j]]);
                bf[j][1] = __float_as_uint(Bs[kr1 + b_n[j]]);
            }
#pragma unroll
            for (int i = 0; i < 4; i++)
#pragma unroll
                for (int j = 0; j < 4; j++) {
                    asm volatile(
                        "mma.sync.aligned.m16n8k8.row.col.f32.tf32.tf32.f32 "
                        "{%0,%1,%2,%3}, {%4,%5,%6,%7}, {%8,%9}, {%0,%1,%2,%3};"
                        : "+f"(acc[i][j][0]), "+f"(acc[i][j][1]),
                          "+f"(acc[i][j][2]), "+f"(acc[i][j][3])
                        : "r"(af[i][0]), "r"(af[i][1]), "r"(af[i][2]), "r"(af[i][3]),
                          "r"(bf[j][0]), "r"(bf[j][1]));
                }
        }
    }

    // epilogue
#pragma unroll
    for (int i = 0; i < 4; i++) {
        int row0 = rowBase + wr * 64 + i * 16 + r;
#pragma unroll
        for (int j = 0; j < 4; j++) {
            int col = colBase + wc * 32 + j * 8 + 2 * cq;
            *(float2*)&C[(size_t)row0 * NN + col] =
                make_float2(acc[i][j][0], acc[i][j][1]);
            *(float2*)&C[(size_t)(row0 + 8) * NN + col] =
                make_float2(acc[i][j][2], acc[i][j][3]);
        }
    }
}

__global__ __launch_bounds__(256, 2) void qkv_gemm() {
    extern __shared__ float smem[];
    const int z = blockIdx.z;
    const float* A = g_tf + OFF_X;
    const float* B = g_tf + OFF_WQ + (size_t)z * UNITS * UNITS;
    float* C = g_QKV + (size_t)z * NTOK * UNITS;
    gemm_body(A, B, C, UNITS, UNITS, smem, blockIdx.y * 128, blockIdx.x * 128);
}

__global__ __launch_bounds__(256, 2) void out_gemm(float* __restrict__ out) {
    extern __shared__ float smem[];
    gemm_body(g_O, g_tf + OFF_WO, out, UNITS, UNITS, smem,
              blockIdx.y * 128, blockIdx.x * 128);
}

// ---------------------------------------------------------------------------
// Block-sparse attention: one CTA per (block, head), 64 threads. Output is
// tf32-rounded on store (out_gemm consumes it raw).
// ---------------------------------------------------------------------------
__global__ __launch_bounds__(64) void attn_kernel(const float* __restrict__ mask) {
    int b = blockIdx.x;
    int h = blockIdx.y;
    int m = g_cnt[b];
    if (m == 0) return;
    int off = g_off[b];

    const float* Q = g_QKV;
    const float* K = g_QKV + NTOK * UNITS;
    const float* V = g_QKV + 2 * NTOK * UNITS;

    __shared__ float Ks[CHK][HDIM];
    __shared__ float Vs[CHK][HDIM];
    __shared__ float Ss[64][CHK + 1];
    __shared__ float bs[CHK];

    int tid = threadIdx.x;

    for (int q0 = 0; q0 < m; q0 += 64) {
        int qi = q0 + tid;
        bool act = qi < m;
        int qt = act ? g_mem[off + qi] : g_mem[off];

        float qreg[HDIM];
        {
            const float4* qp = (const float4*)(Q + (size_t)qt * UNITS + h * HDIM);
#pragma unroll
            for (int i = 0; i < 16; i++) {
                float4 v = qp[i];
                qreg[4 * i + 0] = v.x; qreg[4 * i + 1] = v.y;
                qreg[4 * i + 2] = v.z; qreg[4 * i + 3] = v.w;
            }
        }

        float mx = -3e38f, sm = 0.f;
        float oacc[HDIM];
#pragma unroll
        for (int d = 0; d < HDIM; d++) oacc[d] = 0.f;

        for (int k0 = 0; k0 < m; k0 += CHK) {
            int cn = min(CHK, m - k0);
            __syncthreads();
            {
                int row = tid >> 1;
                int seg = (tid & 1) * 32;
                if (row < cn) {
                    int tk = g_mem[off + k0 + row];
                    const float4* kp = (const float4*)(K + (size_t)tk * UNITS + h * HDIM + seg);
                    const float4* vp = (const float4*)(V + (size_t)tk * UNITS + h * HDIM + seg);
#pragma unroll
                    for (int i = 0; i < 8; i++) {
                        ((float4*)&Ks[row][seg])[i] = kp[i];
                        ((float4*)&Vs[row][seg])[i] = vp[i];
                    }
                    if ((tid & 1) == 0)
                        bs[row] = (1.0f - mask[tk]) * (-1e9f);
                }
            }
            __syncthreads();

            float cm = -3e38f;
            for (int j = 0; j < cn; j++) {
                float s = 0.f;
#pragma unroll
                for (int d = 0; d < HDIM; d++) s += qreg[d] * Ks[j][d];
                s = s * 0.125f + bs[j];
                Ss[tid][j] = s;
                cm = fmaxf(cm, s);
            }
            float nm = fmaxf(mx, cm);
            float corr = __expf(mx - nm);
            sm *= corr;
#pragma unroll
            for (int d = 0; d < HDIM; d++) oacc[d] *= corr;
            for (int j = 0; j < cn; j++) {
                float p = __expf(Ss[tid][j] - nm);
                sm += p;
#pragma unroll
                for (int d = 0; d < HDIM; d++) oacc[d] += p * Vs[j][d];
            }
            mx = nm;
        }

        if (act) {
            float inv = 1.0f / sm;
            float* op = g_O + (size_t)qt * UNITS + h * HDIM;
#pragma unroll
            for (int i = 0; i < 16; i++) {
                float4 v = make_float4(
                    __uint_as_float(f2tf32(oacc[4 * i + 0] * inv)),
                    __uint_as_float(f2tf32(oacc[4 * i + 1] * inv)),
                    __uint_as_float(f2tf32(oacc[4 * i + 2] * inv)),
                    __uint_as_float(f2tf32(oacc[4 * i + 3] * inv)));
                *(float4*)(op + 4 * i) = v;
            }
        }
    }
}

// ---------------------------------------------------------------------------
extern "C" void kernel_launch(void* const* d_in, const int* in_sizes, int n_in,
                              void* d_out, int out_size)
{
    const float* x    = (const float*)d_in[0];
    const float* Wq   = (const float*)d_in[1];
    const float* Wk   = (const float*)d_in[2];
    const float* Wv   = (const float*)d_in[3];
    const float* Wo   = (const float*)d_in[4];
    const float* mask = (const float*)d_in[5];
    const int*   ids  = (const int*)d_in[6];
    float* out = (float*)d_out;

    // Unconditional (no static guard — harness forbids call-count state).
    // Idempotent, not stream-ordered, safe under graph capture.
    cudaFuncSetAttribute(qkv_gemm,
        cudaFuncAttributeMaxDynamicSharedMemorySize, 3 * STAGE_F * 4);
    cudaFuncSetAttribute(out_gemm,
        cudaFuncAttributeMaxDynamicSharedMemorySize, 3 * STAGE_F * 4);

    prep_kernel<<<7168, 256>>>(x, Wq, Wk, Wv, Wo);
    build_index_kernel<<<1, NBLK>>>(ids);

    dim3 gq(UNITS / 128, NTOK / 128, 3);
    qkv_gemm<<<gq, 256, 3 * STAGE_F * 4>>>();

    attn_kernel<<<dim3(NBLK, NHEAD), 64>>>(mask);

    dim3 go(UNITS / 128, NTOK / 128);
    out_gemm<<<go, 256, 3 * STAGE_F * 4>>>(out);
}

// round 6
// speedup vs baseline: 1.7180x; 1.3637x over previous
#include <cuda_runtime.h>
#include <math.h>

#define NTOK  3072
#define UNITS 1024
#define NHEAD 16
#define HDIM  64
#define NBLK  64
#define CHK   32

// tf32-rounded operand pool: [x | Wq | Wk | Wv | Wo]
#define OFF_X  0
#define OFF_WQ (NTOK * UNITS)
#define OFF_WK (OFF_WQ + UNITS * UNITS)
#define OFF_WV (OFF_WK + UNITS * UNITS)
#define OFF_WO (OFF_WV + UNITS * UNITS)
#define TF_TOT (OFF_WO + UNITS * UNITS)

__device__ float g_tf[TF_TOT];
__device__ float g_QKV[3 * NTOK * UNITS];
__device__ float g_O[NTOK * UNITS];
__device__ int   g_cnt[NBLK];
__device__ int   g_off[NBLK];
__device__ int   g_mem[NTOK];

__device__ __forceinline__ unsigned f2tf32(float f) {
    unsigned u;
    asm("cvt.rna.tf32.f32 %0, %1;" : "=r"(u) : "f"(f));
    return u;
}

// ---------------------------------------------------------------------------
// Prep: round x + weights to tf32 once. 1835008 float4s = 7168 blocks x 256.
// ---------------------------------------------------------------------------
__global__ __launch_bounds__(256) void prep_kernel(
    const float* __restrict__ x,  const float* __restrict__ Wq,
    const float* __restrict__ Wk, const float* __restrict__ Wv,
    const float* __restrict__ Wo)
{
    int i = blockIdx.x * 256 + threadIdx.x;   // float4 index
    const float* src; int base;
    if      (i <  786432) { src = x;  base = 0;       }
    else if (i < 1048576) { src = Wq; base = 786432;  }
    else if (i < 1310720) { src = Wk; base = 1048576; }
    else if (i < 1572864) { src = Wv; base = 1310720; }
    else                  { src = Wo; base = 1572864; }
    float4 v = ((const float4*)src)[i - base];
    v.x = __uint_as_float(f2tf32(v.x));
    v.y = __uint_as_float(f2tf32(v.y));
    v.z = __uint_as_float(f2tf32(v.z));
    v.w = __uint_as_float(f2tf32(v.w));
    ((float4*)g_tf)[i] = v;
}

// ---------------------------------------------------------------------------
// Parallel index build: grid=64 (one warp per block id), order-preserving
// warp-ballot ranks. off[b] = #{i: ids[i] < b}; deterministic.
// ---------------------------------------------------------------------------
__global__ __launch_bounds__(32) void build_index_kernel(const int* __restrict__ ids) {
    int b    = blockIdx.x;
    int lane = threadIdx.x;
    int cnt = 0, off = 0;
    for (int i0 = 0; i0 < NTOK; i0 += 32) {
        int id = ids[i0 + lane];
        unsigned meq = __ballot_sync(0xFFFFFFFFu, id == b);
        unsigned mlt = __ballot_sync(0xFFFFFFFFu, id < b);
        cnt += __popc(meq);
        off += __popc(mlt);
    }
    if (lane == 0) { g_cnt[b] = cnt; g_off[b] = off; }
    int run = off;
    unsigned lmask = (1u << lane) - 1u;
    for (int i0 = 0; i0 < NTOK; i0 += 32) {
        int id = ids[i0 + lane];
        unsigned meq = __ballot_sync(0xFFFFFFFFu, id == b);
        if (id == b) g_mem[run + __popc(meq & lmask)] = i0 + lane;
        run += __popc(meq);
    }
}

// ---------------------------------------------------------------------------
// TF32 GEMM, cp.async 3-stage pipeline (unchanged from round 5).
// ---------------------------------------------------------------------------
#define STAGE_F 8192   // floats per stage (A 4096 + B 4096)

__device__ __forceinline__ void cp16(float* dst, const float* src) {
    unsigned d = (unsigned)__cvta_generic_to_shared(dst);
    asm volatile("cp.async.cg.shared.global [%0], [%1], 16;" :: "r"(d), "l"(src));
}

__device__ __forceinline__ void gemm_body(
    const float* __restrict__ A, const float* __restrict__ B,
    float* __restrict__ C, int NN, int K,
    float* smem, int rowBase, int colBase)
{
    const int t    = threadIdx.x;
    const int lane = t & 31;
    const int warp = t >> 5;
    const int wr   = warp >> 2;
    const int wc   = warp & 3;
    const int r    = lane >> 2;
    const int cq   = lane & 3;

    const int am  = t >> 1;
    const int ak0 = (t & 1) * 16;
    const float* Ag = A + (size_t)(rowBase + am) * K + ak0;
    int adst[4];
#pragma unroll
    for (int j = 0; j < 4; j++) {
        int kc = (t & 1) * 4 + j;
        adst[j] = am * 32 + ((kc ^ (am & 7)) * 4);
    }
    const int bkr  = t >> 3;
    const int bn40 = (t & 7) * 4;
    const float* Bg = B + (size_t)bkr * NN + colBase + bn40 * 4;
    int bdst[4];
#pragma unroll
    for (int j = 0; j < 4; j++) {
        int n4 = bn40 + j;
        bdst[j] = bkr * 128 + ((n4 ^ (2 * (bkr & 3))) * 4);
    }

    int a_b0[4], a_b8[4];
#pragma unroll
    for (int i = 0; i < 4; i++) {
        int m0 = wr * 64 + i * 16 + r;
        a_b0[i] = m0 * 32 + cq;
        a_b8[i] = (m0 + 8) * 32 + cq;
    }
    int b_n[4];
#pragma unroll
    for (int j = 0; j < 4; j++)
        b_n[j] = wc * 32 + ((j * 8 + r) ^ (8 * cq));

    float acc[4][4][4];
#pragma unroll
    for (int i = 0; i < 4; i++)
#pragma unroll
        for (int j = 0; j < 4; j++)
#pragma unroll
            for (int e = 0; e < 4; e++) acc[i][j][e] = 0.f;

    const int nT = K / 32;

#pragma unroll
    for (int pt = 0; pt < 2; pt++) {
        float* As = smem + pt * STAGE_F;
        float* Bs = As + 4096;
        const int ko = pt * 32;
#pragma unroll
        for (int j = 0; j < 4; j++) cp16(As + adst[j], Ag + ko + j * 4);
#pragma unroll
        for (int j = 0; j < 4; j++) cp16(Bs + bdst[j], Bg + (size_t)ko * NN + j * 4);
        asm volatile("cp.async.commit_group;" ::: "memory");
    }

    for (int tt = 0; tt < nT; tt++) {
        asm volatile("cp.async.wait_group 1;" ::: "memory");
        __syncthreads();

        if (tt + 2 < nT) {
            int st = (tt + 2) % 3;
            float* As = smem + st * STAGE_F;
            float* Bs = As + 4096;
            const int ko = (tt + 2) * 32;
#pragma unroll
            for (int j = 0; j < 4; j++) cp16(As + adst[j], Ag + ko + j * 4);
#pragma unroll
            for (int j = 0; j < 4; j++) cp16(Bs + bdst[j], Bg + (size_t)ko * NN + j * 4);
        }
        asm volatile("cp.async.commit_group;" ::: "memory");

        const float* As = smem + (tt % 3) * STAGE_F;
        const float* Bs = As + 4096;
#pragma unroll
        for (int ks = 0; ks < 4; ks++) {
            const int q0 = ((2 * ks) ^ r) * 4;
            const int q1 = ((2 * ks + 1) ^ r) * 4;
            unsigned af[4][4];
#pragma unroll
            for (int i = 0; i < 4; i++) {
                af[i][0] = __float_as_uint(As[a_b0[i] + q0]);
                af[i][1] = __float_as_uint(As[a_b8[i] + q0]);
                af[i][2] = __float_as_uint(As[a_b0[i] + q1]);
                af[i][3] = __float_as_uint(As[a_b8[i] + q1]);
            }
            const int kr0 = (ks * 8 + cq) * 128;
            const int kr1 = kr0 + 4 * 128;
            unsigned bf[4][2];
#pragma unroll
            for (int j = 0; j < 4; j++) {
                bf[j][0] = __float_as_uint(Bs[kr0 + b_n[j]]);
                bf[j][1] = __float_as_uint(Bs[kr1 + b_n[j]]);
            }
#pragma unroll
            for (int i = 0; i < 4; i++)
#pragma unroll
                for (int j = 0; j < 4; j++) {
                    asm volatile(
                        "mma.sync.aligned.m16n8k8.row.col.f32.tf32.tf32.f32 "
                        "{%0,%1,%2,%3}, {%4,%5,%6,%7}, {%8,%9}, {%0,%1,%2,%3};"
                        : "+f"(acc[i][j][0]), "+f"(acc[i][j][1]),
                          "+f"(acc[i][j][2]), "+f"(acc[i][j][3])
                        : "r"(af[i][0]), "r"(af[i][1]), "r"(af[i][2]), "r"(af[i][3]),
                          "r"(bf[j][0]), "r"(bf[j][1]));
                }
        }
    }

#pragma unroll
    for (int i = 0; i < 4; i++) {
        int row0 = rowBase + wr * 64 + i * 16 + r;
#pragma unroll
        for (int j = 0; j < 4; j++) {
            int col = colBase + wc * 32 + j * 8 + 2 * cq;
            *(float2*)&C[(size_t)row0 * NN + col] =
                make_float2(acc[i][j][0], acc[i][j][1]);
            *(float2*)&C[(size_t)(row0 + 8) * NN + col] =
                make_float2(acc[i][j][2], acc[i][j][3]);
        }
    }
}

__global__ __launch_bounds__(256, 2) void qkv_gemm() {
    extern __shared__ float smem[];
    const int z = blockIdx.z;
    const float* A = g_tf + OFF_X;
    const float* B = g_tf + OFF_WQ + (size_t)z * UNITS * UNITS;
    float* C = g_QKV + (size_t)z * NTOK * UNITS;
    gemm_body(A, B, C, UNITS, UNITS, smem, blockIdx.y * 128, blockIdx.x * 128);
}

__global__ __launch_bounds__(256, 2) void out_gemm(float* __restrict__ out) {
    extern __shared__ float smem[];
    gemm_body(g_O, g_tf + OFF_WO, out, UNITS, UNITS, smem,
              blockIdx.y * 128, blockIdx.x * 128);
}

// ---------------------------------------------------------------------------
// Block-sparse attention: one CTA per (block, head), 128 threads = 64 query
// slots x 2 dim-halves. Fully-online softmax (no score storage). K/V smem
// halves offset by +36 words (row stride 68) -> even/odd half reads hit
// different banks; same-address reads broadcast.
// ---------------------------------------------------------------------------
#define KVSTR 68   // row stride in floats; half 0 at +0, half 1 at +36

__global__ __launch_bounds__(128) void attn_kernel(const float* __restrict__ mask) {
    int b = blockIdx.x;
    int h = blockIdx.y;
    int m = g_cnt[b];
    if (m == 0) return;
    int off = g_off[b];

    const float* Q = g_QKV;
    const float* K = g_QKV + NTOK * UNITS;
    const float* V = g_QKV + 2 * NTOK * UNITS;

    __shared__ float Ks[CHK * KVSTR];
    __shared__ float Vs[CHK * KVSTR];
    __shared__ float bs[CHK];

    const int tid   = threadIdx.x;
    const int slot  = tid >> 1;
    const int half  = tid & 1;
    const int dbase = half * 32;          // global dim offset
    const int sbase = half * 36;          // smem half offset

    for (int q0 = 0; q0 < m; q0 += 64) {
        int qi = q0 + slot;
        bool act = qi < m;
        int qt = act ? g_mem[off + qi] : g_mem[off];

        float qreg[32];
        {
            const float4* qp = (const float4*)(Q + (size_t)qt * UNITS + h * HDIM + dbase);
#pragma unroll
            for (int i = 0; i < 8; i++) {
                float4 v = qp[i];
                qreg[4 * i + 0] = v.x; qreg[4 * i + 1] = v.y;
                qreg[4 * i + 2] = v.z; qreg[4 * i + 3] = v.w;
            }
        }

        float mx = -3e38f, sm = 0.f;
        float oacc[32];
#pragma unroll
        for (int d = 0; d < 32; d++) oacc[d] = 0.f;

        for (int k0 = 0; k0 < m; k0 += CHK) {
            int cn = min(CHK, m - k0);
            __syncthreads();
            {
                int row = tid >> 2;              // 0..31
                int seg = (tid & 3) * 16;        // 0/16/32/48
                int adj = seg + ((seg >= 32) ? 4 : 0);  // smem col (half1 at +36)
                if (row < cn) {
                    int tk = g_mem[off + k0 + row];
                    const float4* kp = (const float4*)(K + (size_t)tk * UNITS + h * HDIM + seg);
                    const float4* vp = (const float4*)(V + (size_t)tk * UNITS + h * HDIM + seg);
                    float4* kd = (float4*)&Ks[row * KVSTR + adj];
                    float4* vd = (float4*)&Vs[row * KVSTR + adj];
#pragma unroll
                    for (int i = 0; i < 4; i++) { kd[i] = kp[i]; vd[i] = vp[i]; }
                    if ((tid & 3) == 0)
                        bs[row] = (1.0f - mask[tk]) * (-1e9f);
                }
            }
            __syncthreads();

            for (int j = 0; j < cn; j++) {
                const float* kr = &Ks[j * KVSTR + sbase];
                float partial = 0.f;
#pragma unroll
                for (int d = 0; d < 32; d++) partial += qreg[d] * kr[d];
                float s = partial + __shfl_xor_sync(0xFFFFFFFFu, partial, 1);
                s = s * 0.125f + bs[j];

                if (s > mx) {
                    float corr = __expf(mx - s);
                    sm *= corr;
#pragma unroll
                    for (int d = 0; d < 32; d++) oacc[d] *= corr;
                    mx = s;
                }
                float p = __expf(s - mx);
                sm += p;
                const float* vr = &Vs[j * KVSTR + sbase];
#pragma unroll
                for (int d = 0; d < 32; d++) oacc[d] += p * vr[d];
            }
        }

        if (act) {
            float inv = 1.0f / sm;
            float* op = g_O + (size_t)qt * UNITS + h * HDIM + dbase;
#pragma unroll
            for (int i = 0; i < 8; i++) {
                float4 v = make_float4(
                    __uint_as_float(f2tf32(oacc[4 * i + 0] * inv)),
                    __uint_as_float(f2tf32(oacc[4 * i + 1] * inv)),
                    __uint_as_float(f2tf32(oacc[4 * i + 2] * inv)),
                    __uint_as_float(f2tf32(oacc[4 * i + 3] * inv)));
                *(float4*)(op + 4 * i) = v;
            }
        }
    }
}

// ---------------------------------------------------------------------------
extern "C" void kernel_launch(void* const* d_in, const int* in_sizes, int n_in,
                              void* d_out, int out_size)
{
    const float* x    = (const float*)d_in[0];
    const float* Wq   = (const float*)d_in[1];
    const float* Wk   = (const float*)d_in[2];
    const float* Wv   = (const float*)d_in[3];
    const float* Wo   = (const float*)d_in[4];
    const float* mask = (const float*)d_in[5];
    const int*   ids  = (const int*)d_in[6];
    float* out = (float*)d_out;

    cudaFuncSetAttribute(qkv_gemm,
        cudaFuncAttributeMaxDynamicSharedMemorySize, 3 * STAGE_F * 4);
    cudaFuncSetAttribute(out_gemm,
        cudaFuncAttributeMaxDynamicSharedMemorySize, 3 * STAGE_F * 4);

    prep_kernel<<<7168, 256>>>(x, Wq, Wk, Wv, Wo);
    build_index_kernel<<<NBLK, 32>>>(ids);

    dim3 gq(UNITS / 128, NTOK / 128, 3);
    qkv_gemm<<<gq, 256, 3 * STAGE_F * 4>>>();

    attn_kernel<<<dim3(NBLK, NHEAD), 128>>>(mask);

    dim3 go(UNITS / 128, NTOK / 128);
    out_gemm<<<go, 256, 3 * STAGE_F * 4>>>(out);
}